// round 15
// baseline (speedup 1.0000x reference)
#include <cuda_runtime.h>
#include <cstdint>

#define BB   8
#define SEQ  2048
#define DIM  512

// Scratch (device globals; no allocs allowed)
__device__ float g_QK   [2 * (size_t)BB * SEQ * DIM];  // Q | K
__device__ float g_Vt   [(size_t)BB * SEQ * DIM];      // V transposed [b][d][s]
__device__ float g_S    [(size_t)BB * SEQ * SEQ];      // scores -> P (exp'd)
__device__ float g_Xr   [(size_t)BB * SEQ * DIM];      // tf32-rounded x
__device__ float g_Wr   [3 * (size_t)DIM * DIM];       // tf32-rounded Wq|Wk|Wv
__device__ float g_b    [3 * DIM];                     // packed bq|bk|bv
__device__ float g_Spart[16 * (size_t)BB * SEQ];       // per-coltile row sums
__device__ float g_rsum [(size_t)BB * SEQ];            // full row sums

__device__ __forceinline__ uint32_t tf32cvt(float f) {
    uint32_t r; asm("cvt.rna.tf32.f32 %0, %1;" : "=r"(r) : "f"(f)); return r;
}
__device__ __forceinline__ float tf32round(float f) {
    return __uint_as_float(tf32cvt(f));
}
__device__ __forceinline__ uint32_t smem_u32(const void* p) {
    uint32_t a;
    asm("{ .reg .u64 t; cvta.to.shared.u64 t, %1; cvt.u32.u64 %0, t; }" : "=r"(a) : "l"(p));
    return a;
}
__device__ __forceinline__ void ldsm4(uint32_t* r, uint32_t addr) {
    asm volatile("ldmatrix.sync.aligned.m8n8.x4.shared.b16 {%0,%1,%2,%3}, [%4];"
                 : "=r"(r[0]), "=r"(r[1]), "=r"(r[2]), "=r"(r[3]) : "r"(addr));
}
#define CP_ASYNC16(s, g) \
    asm volatile("cp.async.cg.shared.global [%0], [%1], 16;" :: "r"(s), "l"(g))
#define CP_COMMIT() asm volatile("cp.async.commit_group;" ::: "memory")
#define CP_WAIT1()  asm volatile("cp.async.wait_group 1;"  ::: "memory")

#define MMA_TF32(d, a, b) \
    asm volatile( \
        "mma.sync.aligned.m16n8k8.row.col.f32.tf32.tf32.f32 " \
        "{%0,%1,%2,%3}, {%4,%5,%6,%7}, {%8,%9}, {%0,%1,%2,%3};" \
        : "+f"((d)[0]), "+f"((d)[1]), "+f"((d)[2]), "+f"((d)[3]) \
        : "r"((a)[0]), "r"((a)[1]), "r"((a)[2]), "r"((a)[3]), \
          "r"((b)[0]), "r"((b)[1]))

#define SW(o) ((o) ^ (((o) >> 3) & 0x70))

#define TM 128
#define TK 32
#define NSTAGE 3

// Epilogue modes
#define EPI_PROJ  0   // +bias[col], tf32-round
#define EPI_SOFT  1   // exp(scale*s) with mask, tf32-round, partial row sums
#define EPI_AV    2   // divide rows by rsum
#define EPI_PROJT 3   // +bias[row], tf32-round (transposed projection)

constexpr int smem_for(int NI) { return NSTAGE * (16384 + 32 * NI * 128) + 1024; }

// ---------------------------------------------------------------------------
// tf32 mma.sync GEMM:  C = epi( A @ B^T )
// A: [M x K] row-major, B: [N x K] row-major; BOTH ALREADY tf32-ROUNDED.
// NI = n-fragments per warp: 4 -> CTA tile 128x128 (2 CTA/SM, frag dbuf),
//                            8 -> CTA tile 128x256 (1 CTA/SM, single buf).
// 256 threads = 8 warps (2m x 4n). 3-stage cp.async pipeline, ldmatrix
// fragments via unswizzled base + constant XOR mask.
// ---------------------------------------------------------------------------
template<int LDA, int LDB, int LDC, int K, int EPI, int NI>
__global__ void __launch_bounds__(256, NI == 4 ? 2 : 1)
gemm_mma(const float* __restrict__ A, const float* __restrict__ B,
         float* __restrict__ C,
         const float* __restrict__ bias, const int* __restrict__ mask,
         float* __restrict__ spart, const float* __restrict__ rsum,
         long sA, long sB, long sC, float scale)
{
    constexpr int TN  = 32 * NI;
    constexpr int SB  = 16384 + TN * 128;       // stage bytes (A 16KB + B)
    constexpr int BU  = TN / 32;                // B cp.async row-groups
    constexpr int DBF = (NI == 4) ? 2 : 1;      // fragment buffers

    extern __shared__ char smraw[];
    const uint32_t sbase = (smem_u32(smraw) + 1023u) & ~1023u;

    const int tid = threadIdx.x;
    const int wid = tid >> 5;
    const int lid = tid & 31;
    const int g   = lid >> 2;
    const int t   = lid & 3;

    const int bz = blockIdx.z;
    A += (long)bz * sA;  B += (long)bz * sB;  C += (long)bz * sC;
    const int bm = blockIdx.y * TM;
    const int bn = blockIdx.x * TN;

    const int wm = (wid >> 2) * 64;
    const int wn = (wid & 3) * (NI * 8);

    const int aRowL = lid & 15;
    const int akh   = lid >> 4;
    const int bRowL = (lid & 7) + ((lid >> 4) & 1) * 8;
    const int bkh   = (lid >> 3) & 1;

    const int ldr  = tid >> 3;
    const int lc16 = tid & 7;

    const float* aN = A + (long)(bm + ldr) * LDA + lc16 * 4;
    const float* bN = B + (long)(bn + ldr) * LDB + lc16 * 4;
    const uint32_t so0 = SW((ldr << 7) + (lc16 << 4));   // +u*4096 carry-free

    const uint32_t aU0   = sbase + ((wm + aRowL) << 7) + (akh << 4);
    const uint32_t bU0   = sbase + 16384 + ((wn + bRowL) << 7) + (bkh << 4);
    const uint32_t maskA = (uint32_t)(aRowL & 7) << 4;
    const uint32_t maskB = (uint32_t)(lid & 7) << 4;

    float acc[4][NI][4];
#pragma unroll
    for (int i = 0; i < 4; i++)
#pragma unroll
        for (int j = 0; j < NI; j++)
#pragma unroll
            for (int r = 0; r < 4; r++) acc[i][j][r] = 0.f;

    const int nc = K / TK;

    uint32_t ist = 0;     // issue-stage byte offset (rotating)
    auto issue = [&]() {
        const uint32_t As = sbase + ist + so0;
#pragma unroll
        for (int u = 0; u < 4; u++)
            CP_ASYNC16(As + u * 4096, aN + u * 32 * LDA);
#pragma unroll
        for (int u = 0; u < BU; u++)
            CP_ASYNC16(As + 16384 + u * 4096, bN + u * 32 * LDB);
        aN += TK;  bN += TK;
        ist += SB; if (ist == NSTAGE * SB) ist = 0;
    };

    uint32_t af[DBF][4][4], bf[DBF][NI / 2][4];
    auto ldfrag = [&](uint32_t stoff, int ks, int buf) {
#pragma unroll
        for (int mi = 0; mi < 4; mi++)
            ldsm4(af[buf][mi], (aU0 + stoff + mi * 2048 + ks * 32) ^ maskA);
#pragma unroll
        for (int nb = 0; nb < NI / 2; nb++)
            ldsm4(bf[buf][nb], (bU0 + stoff + nb * 2048 + ks * 32) ^ maskB);
    };

    issue(); CP_COMMIT();
    issue(); CP_COMMIT();

    uint32_t cst = 0;     // compute-stage byte offset (rotating)
    for (int c = 0; c < nc; c++) {
        CP_WAIT1();
        __syncthreads();

        if (DBF == 2) {
            ldfrag(cst, 0, 0);
            if (c + 2 < nc) issue();
            CP_COMMIT();
#pragma unroll
            for (int ks = 0; ks < 4; ks++) {
                if (ks < 3) ldfrag(cst, ks + 1, (ks + 1) % DBF);
                const int cur = ks % DBF;
#pragma unroll
                for (int mi = 0; mi < 4; mi++)
#pragma unroll
                    for (int ni = 0; ni < NI; ni++)
                        MMA_TF32(acc[mi][ni], af[cur][mi], &bf[cur][ni >> 1][(ni & 1) * 2]);
            }
        } else {
            if (c + 2 < nc) issue();
            CP_COMMIT();
#pragma unroll
            for (int ks = 0; ks < 4; ks++) {
                ldfrag(cst, ks, 0);
#pragma unroll
                for (int mi = 0; mi < 4; mi++)
#pragma unroll
                    for (int ni = 0; ni < NI; ni++)
                        MMA_TF32(acc[mi][ni], af[0][mi], &bf[0][ni >> 1][(ni & 1) * 2]);
            }
        }
        cst += SB; if (cst == NSTAGE * SB) cst = 0;
    }

    // ======================= epilogues =======================
    if (EPI == EPI_PROJ) {
        bias += (long)bz * DIM;
#pragma unroll
        for (int mi = 0; mi < 4; mi++) {
            const int row0 = bm + wm + mi * 16 + g;
#pragma unroll
            for (int ni = 0; ni < NI; ni++) {
                const int col = bn + wn + ni * 8 + 2 * t;
                const float bx = bias[col], by = bias[col + 1];
                float2 v0, v1;
                v0.x = tf32round(acc[mi][ni][0] + bx);
                v0.y = tf32round(acc[mi][ni][1] + by);
                v1.x = tf32round(acc[mi][ni][2] + bx);
                v1.y = tf32round(acc[mi][ni][3] + by);
                *(float2*)(C + (long)row0 * LDC + col)       = v0;
                *(float2*)(C + (long)(row0 + 8) * LDC + col) = v1;
            }
        }
    } else if (EPI == EPI_PROJT) {
#pragma unroll
        for (int mi = 0; mi < 4; mi++) {
            const int row0 = bm + wm + mi * 16 + g;
            const float b0 = bias[row0];
            const float b8 = bias[row0 + 8];
#pragma unroll
            for (int ni = 0; ni < NI; ni++) {
                const int col = bn + wn + ni * 8 + 2 * t;
                float2 v0, v1;
                v0.x = tf32round(acc[mi][ni][0] + b0);
                v0.y = tf32round(acc[mi][ni][1] + b0);
                v1.x = tf32round(acc[mi][ni][2] + b8);
                v1.y = tf32round(acc[mi][ni][3] + b8);
                *(float2*)(C + (long)row0 * LDC + col)       = v0;
                *(float2*)(C + (long)(row0 + 8) * LDC + col) = v1;
            }
        }
    } else if (EPI == EPI_SOFT) {
        mask += (long)bz * SEQ;
        int mk[2 * NI];
#pragma unroll
        for (int ni = 0; ni < NI; ni++) {
            const int col = bn + wn + ni * 8 + 2 * t;
            mk[ni * 2]     = mask[col];
            mk[ni * 2 + 1] = mask[col + 1];
        }
        __syncthreads();                       // smem stages -> scratch reuse
        float* part = (float*)smraw;           // [4][128] floats
        const int wnidx = wid & 3;
#pragma unroll
        for (int mi = 0; mi < 4; mi++) {
            const int rloc = wm + mi * 16 + g; // 0..127
            const int row0 = bm + rloc;
            float s0 = 0.f, s8 = 0.f;
#pragma unroll
            for (int ni = 0; ni < NI; ni++) {
                const int col = bn + wn + ni * 8 + 2 * t;
                float e0 = mk[ni * 2]     ? tf32round(__expf(acc[mi][ni][0] * scale)) : 0.f;
                float e1 = mk[ni * 2 + 1] ? tf32round(__expf(acc[mi][ni][1] * scale)) : 0.f;
                float e2 = mk[ni * 2]     ? tf32round(__expf(acc[mi][ni][2] * scale)) : 0.f;
                float e3 = mk[ni * 2 + 1] ? tf32round(__expf(acc[mi][ni][3] * scale)) : 0.f;
                *(float2*)(C + (long)row0 * LDC + col)       = make_float2(e0, e1);
                *(float2*)(C + (long)(row0 + 8) * LDC + col) = make_float2(e2, e3);
                s0 += e0 + e1;
                s8 += e2 + e3;
            }
            s0 += __shfl_xor_sync(0xFFFFFFFF, s0, 1);
            s0 += __shfl_xor_sync(0xFFFFFFFF, s0, 2);
            s8 += __shfl_xor_sync(0xFFFFFFFF, s8, 1);
            s8 += __shfl_xor_sync(0xFFFFFFFF, s8, 2);
            if (t == 0) {
                part[wnidx * 128 + rloc]     = s0;
                part[wnidx * 128 + rloc + 8] = s8;
            }
        }
        __syncthreads();
        if (tid < 128) {
            const float r = part[tid] + part[128 + tid] + part[256 + tid] + part[384 + tid];
            spart[(long)blockIdx.x * (BB * SEQ) + (long)bz * SEQ + bm + tid] = r;
        }
    } else { // EPI_AV
        rsum += (long)bz * SEQ;
#pragma unroll
        for (int mi = 0; mi < 4; mi++) {
            const int row0 = bm + wm + mi * 16 + g;
            const float inv0 = 1.f / rsum[row0];
            const float inv8 = 1.f / rsum[row0 + 8];
#pragma unroll
            for (int ni = 0; ni < NI; ni++) {
                const int col = bn + wn + ni * 8 + 2 * t;
                float2 v0, v1;
                v0.x = acc[mi][ni][0] * inv0;
                v0.y = acc[mi][ni][1] * inv0;
                v1.x = acc[mi][ni][2] * inv8;
                v1.y = acc[mi][ni][3] * inv8;
                *(float2*)(C + (long)row0 * LDC + col)       = v0;
                *(float2*)(C + (long)(row0 + 8) * LDC + col) = v1;
            }
        }
    }
}

// ---------------------------------------------------------------------------
// Fold NT per-coltile partial sums -> full row sums. Deterministic.
// ---------------------------------------------------------------------------
__global__ __launch_bounds__(256) void rowsum_kernel(
    const float* __restrict__ spart, float* __restrict__ rsum, int nt)
{
    const int r = blockIdx.x * blockDim.x + threadIdx.x;
    float s = 0.f;
    for (int t = 0; t < nt; t++)
        s += spart[(long)t * (BB * SEQ) + r];
    rsum[r] = s;
}

// ---------------------------------------------------------------------------
// Single prepass: round x -> Xr, Wq/Wk/Wv -> Wr slots, pack biases.
// ---------------------------------------------------------------------------
__global__ __launch_bounds__(256) void prep_kernel(
    const float4* __restrict__ x,
    const float4* __restrict__ wq, const float4* __restrict__ wk,
    const float4* __restrict__ wv,
    const float4* __restrict__ bq, const float4* __restrict__ bk,
    const float4* __restrict__ bv,
    float4* __restrict__ xr, float4* __restrict__ wr, float4* __restrict__ bdst,
    int xN4, int wN4)
{
    const int i = blockIdx.x * blockDim.x + threadIdx.x;
    auto rnd = [](float4 v) {
        v.x = tf32round(v.x); v.y = tf32round(v.y);
        v.z = tf32round(v.z); v.w = tf32round(v.w);
        return v;
    };
    if (i < xN4) {
        xr[i] = rnd(x[i]);
    } else {
        int j = i - xN4;
        if (j < 3 * wN4) {
            const int s = j / wN4, o = j - s * wN4;
            const float4* src = (s == 0) ? wq : (s == 1) ? wk : wv;
            wr[s * wN4 + o] = rnd(src[o]);
        } else {
            int k = j - 3 * wN4;
            if (k < 3 * (DIM / 4)) {
                const int s = k / (DIM / 4), o = k - s * (DIM / 4);
                const float4* src = (s == 0) ? bq : (s == 1) ? bk : bv;
                bdst[s * (DIM / 4) + o] = src[o];
            }
        }
    }
}

// ---------------------------------------------------------------------------
extern "C" void kernel_launch(void* const* d_in, const int* in_sizes, int n_in,
                              void* d_out, int out_size)
{
    const float* x    = (const float*)d_in[0];
    const int*   mask = (const int*)  d_in[1];
    const float* Wk   = (const float*)d_in[2];
    const float* bk   = (const float*)d_in[3];
    const float* Wq   = (const float*)d_in[4];
    const float* bq   = (const float*)d_in[5];
    const float* Wv   = (const float*)d_in[6];
    const float* bv   = (const float*)d_in[7];
    float* out = (float*)d_out;

    float *QK, *Vt, *S, *Xr, *Wr, *bias, *Spart, *rsum;
    cudaGetSymbolAddress((void**)&QK,    g_QK);
    cudaGetSymbolAddress((void**)&Vt,    g_Vt);
    cudaGetSymbolAddress((void**)&S,     g_S);
    cudaGetSymbolAddress((void**)&Xr,    g_Xr);
    cudaGetSymbolAddress((void**)&Wr,    g_Wr);
    cudaGetSymbolAddress((void**)&bias,  g_b);
    cudaGetSymbolAddress((void**)&Spart, g_Spart);
    cudaGetSymbolAddress((void**)&rsum,  g_rsum);

    const size_t PLANE = (size_t)BB * SEQ * DIM;
    float* Q  = QK;
    float* Kp = QK + PLANE;

    auto projK  = gemm_mma<DIM, DIM, DIM, DIM, EPI_PROJ,  4>;
    auto projTK = gemm_mma<DIM, DIM, SEQ, DIM, EPI_PROJT, 4>;
    auto scorK  = gemm_mma<DIM, DIM, SEQ, DIM, EPI_SOFT,  8>;
    auto avK    = gemm_mma<SEQ, SEQ, DIM, SEQ, EPI_AV,    8>;
    cudaFuncSetAttribute(projK,  cudaFuncAttributeMaxDynamicSharedMemorySize, smem_for(4));
    cudaFuncSetAttribute(projTK, cudaFuncAttributeMaxDynamicSharedMemorySize, smem_for(4));
    cudaFuncSetAttribute(scorK,  cudaFuncAttributeMaxDynamicSharedMemorySize, smem_for(8));
    cudaFuncSetAttribute(avK,    cudaFuncAttributeMaxDynamicSharedMemorySize, smem_for(8));

    // single prepass launch (Wr slots: 0=Wq, 1=Wk, 2=Wv; bias: bq|bk|bv)
    const int xN4 = BB * SEQ * DIM / 4;
    const int wN4 = DIM * DIM / 4;
    const int tot = xN4 + 3 * wN4 + 3 * (DIM / 4);
    prep_kernel<<<(tot + 255) / 256, 256>>>(
        (const float4*)x,
        (const float4*)Wq, (const float4*)Wk, (const float4*)Wv,
        (const float4*)bq, (const float4*)bk, (const float4*)bv,
        (float4*)Xr, (float4*)Wr, (float4*)bias, xN4, wN4);

    // Q/K projections: grid.z in {0,1} selects (W, bias, output plane)
    dim3 gp(DIM / 128, (BB * SEQ) / TM, 2);
    projK<<<gp, 256, smem_for(4)>>>(Xr, Wr, QK, bias, nullptr, nullptr, nullptr,
                                    0, (long)DIM * DIM, (long)PLANE, 1.f);

    // Vt projection, directly transposed: Vt[b] = Wv @ Xr[b]^T + bv (row bias)
    dim3 gt(SEQ / 128, DIM / TM, BB);
    projTK<<<gt, 256, smem_for(4)>>>(Wr + 2L * DIM * DIM, Xr, Vt,
                                     bias + 2L * DIM, nullptr, nullptr, nullptr,
                                     0, (long)SEQ * DIM, (long)SEQ * DIM, 1.f);

    // scores + masked exp + partial row sums:  P[b] = exp(Q K^T / sqrt(D))
    const float inv_sqrt_d = 0.044194173824159216f;
    dim3 gs(SEQ / 256, SEQ / TM, BB);
    scorK<<<gs, 256, smem_for(8)>>>(Q, Kp, S, nullptr, mask, Spart, nullptr,
                                    (long)SEQ * DIM, (long)SEQ * DIM, (long)SEQ * SEQ,
                                    inv_sqrt_d);

    // fold partial sums (8 col-tiles of 256)
    rowsum_kernel<<<(BB * SEQ) / 256, 256>>>(Spart, rsum, SEQ / 256);

    // out[b] = (P[b] @ Vt[b]^T) / rowsum
    dim3 ga(DIM / 256, SEQ / TM, BB);
    avK<<<ga, 256, smem_for(8)>>>(S, Vt, out, nullptr, nullptr, nullptr, rsum,
                                  (long)SEQ * SEQ, (long)SEQ * DIM, (long)SEQ * DIM,
                                  1.f);
}

// round 16
// speedup vs baseline: 1.0771x; 1.0771x over previous
#include <cuda_runtime.h>
#include <cstdint>

#define BB   8
#define SEQ  2048
#define DIM  512

// Scratch (device globals; no allocs allowed)
__device__ float g_QK   [2 * (size_t)BB * SEQ * DIM];  // Q | K
__device__ float g_Vt   [(size_t)BB * SEQ * DIM];      // V transposed [b][d][s]
__device__ float g_S    [(size_t)BB * SEQ * SEQ];      // scores -> P (exp'd)
__device__ float g_Xr   [(size_t)BB * SEQ * DIM];      // tf32-rounded x
__device__ float g_Wr   [3 * (size_t)DIM * DIM];       // tf32-rounded Wq|Wk|Wv
__device__ float g_b    [3 * DIM];                     // packed bq|bk|bv
__device__ float g_Spart[16 * (size_t)BB * SEQ];       // per-coltile row sums
__device__ float g_rsum [(size_t)BB * SEQ];            // full row sums

__device__ __forceinline__ uint32_t tf32cvt(float f) {
    uint32_t r; asm("cvt.rna.tf32.f32 %0, %1;" : "=r"(r) : "f"(f)); return r;
}
__device__ __forceinline__ float tf32round(float f) {
    return __uint_as_float(tf32cvt(f));
}
__device__ __forceinline__ uint32_t smem_u32(const void* p) {
    uint32_t a;
    asm("{ .reg .u64 t; cvta.to.shared.u64 t, %1; cvt.u32.u64 %0, t; }" : "=r"(a) : "l"(p));
    return a;
}
__device__ __forceinline__ void ldsm4(uint32_t* r, uint32_t addr) {
    asm volatile("ldmatrix.sync.aligned.m8n8.x4.shared.b16 {%0,%1,%2,%3}, [%4];"
                 : "=r"(r[0]), "=r"(r[1]), "=r"(r[2]), "=r"(r[3]) : "r"(addr));
}
#define CP_ASYNC16(s, g) \
    asm volatile("cp.async.cg.shared.global [%0], [%1], 16;" :: "r"(s), "l"(g))
#define CP_COMMIT() asm volatile("cp.async.commit_group;" ::: "memory")
#define CP_WAIT1()  asm volatile("cp.async.wait_group 1;"  ::: "memory")

#define MMA_TF32(d, a, b) \
    asm volatile( \
        "mma.sync.aligned.m16n8k8.row.col.f32.tf32.tf32.f32 " \
        "{%0,%1,%2,%3}, {%4,%5,%6,%7}, {%8,%9}, {%0,%1,%2,%3};" \
        : "+f"((d)[0]), "+f"((d)[1]), "+f"((d)[2]), "+f"((d)[3]) \
        : "r"((a)[0]), "r"((a)[1]), "r"((a)[2]), "r"((a)[3]), \
          "r"((b)[0]), "r"((b)[1]))

#define SW(o) ((o) ^ (((o) >> 3) & 0x70))

#define TM 128
#define TN 128
#define TK 32
#define NSTAGE 3
#define STAGE_BYTES 32768
#define GEMM_SMEM (NSTAGE * STAGE_BYTES + 1024)

// Epilogue modes
#define EPI_PROJ  0   // +bias[col], tf32-round
#define EPI_SOFT  1   // exp(scale*s) with mask, tf32-round, partial row sums
#define EPI_AV    2   // divide rows by rsum
#define EPI_PROJT 3   // +bias[row], tf32-round (transposed projection)

// ---------------------------------------------------------------------------
// tf32 mma.sync GEMM body:  C = epi( A @ B^T )
// A: [M x K] row-major, B: [N x K] row-major; BOTH ALREADY tf32-ROUNDED.
// CTA tile 128x128, 256 threads = 8 warps (2m x 4n), warp tile 64x32,
// ldmatrix fragments (unswizzled base + constant XOR mask), 3-stage
// cp.async pipeline + per-ks fragment double buffering. 2 CTA/SM.
// Takes explicit block coords so callers can fuse grids.
// ---------------------------------------------------------------------------
template<int LDA, int LDB, int LDC, int K, int EPI>
__device__ __forceinline__ void gemm_body(
    int bx, int by, int bz,
    const float* __restrict__ A, const float* __restrict__ B,
    float* __restrict__ C,
    const float* __restrict__ bias, const int* __restrict__ mask,
    float* __restrict__ spart, const float* __restrict__ rsum,
    long sA, long sB, long sC, float scale, char* smraw)
{
    const uint32_t sbase = (smem_u32(smraw) + 1023u) & ~1023u;

    const int tid = threadIdx.x;
    const int wid = tid >> 5;
    const int lid = tid & 31;
    const int g   = lid >> 2;
    const int t   = lid & 3;

    A += (long)bz * sA;  B += (long)bz * sB;  C += (long)bz * sC;
    const int bm = by * TM;
    const int bn = bx * TN;

    const int wm = (wid >> 2) * 64;
    const int wn = (wid & 3) * 32;

    const int aRowL = lid & 15;
    const int akh   = lid >> 4;
    const int bRowL = (lid & 7) + ((lid >> 4) & 1) * 8;
    const int bkh   = (lid >> 3) & 1;

    const int ldr  = tid >> 3;
    const int lc16 = tid & 7;

    const float* aN = A + (long)(bm + ldr) * LDA + lc16 * 4;
    const float* bN = B + (long)(bn + ldr) * LDB + lc16 * 4;
    const uint32_t so0 = SW((ldr << 7) + (lc16 << 4));   // +u*4096 carry-free

    const uint32_t aU0   = sbase + ((wm + aRowL) << 7) + (akh << 4);
    const uint32_t bU0   = sbase + 16384 + ((wn + bRowL) << 7) + (bkh << 4);
    const uint32_t maskA = (uint32_t)(aRowL & 7) << 4;
    const uint32_t maskB = (uint32_t)(lid & 7) << 4;

    float acc[4][4][4];
#pragma unroll
    for (int i = 0; i < 4; i++)
#pragma unroll
        for (int j = 0; j < 4; j++)
#pragma unroll
            for (int r = 0; r < 4; r++) acc[i][j][r] = 0.f;

    const int nc = K / TK;

    uint32_t ist = 0;     // issue-stage byte offset (rotating)
    auto issue = [&]() {
        const uint32_t As = sbase + ist + so0;
#pragma unroll
        for (int u = 0; u < 4; u++) {
            CP_ASYNC16(As + u * 4096,         aN + u * 32 * LDA);
            CP_ASYNC16(As + 16384 + u * 4096, bN + u * 32 * LDB);
        }
        aN += TK;  bN += TK;
        ist += STAGE_BYTES; if (ist == NSTAGE * STAGE_BYTES) ist = 0;
    };

    uint32_t af[2][4][4], bf[2][2][4];
    auto ldfrag = [&](uint32_t stoff, int ks, int buf) {
#pragma unroll
        for (int mi = 0; mi < 4; mi++)
            ldsm4(af[buf][mi], (aU0 + stoff + mi * 2048 + ks * 32) ^ maskA);
#pragma unroll
        for (int nb = 0; nb < 2; nb++)
            ldsm4(bf[buf][nb], (bU0 + stoff + nb * 2048 + ks * 32) ^ maskB);
    };

    issue(); CP_COMMIT();
    issue(); CP_COMMIT();

    uint32_t cst = 0;     // compute-stage byte offset (rotating)
    for (int c = 0; c < nc; c++) {
        CP_WAIT1();
        __syncthreads();

        ldfrag(cst, 0, 0);
        if (c + 2 < nc) issue();
        CP_COMMIT();

#pragma unroll
        for (int ks = 0; ks < 4; ks++) {
            if (ks < 3) ldfrag(cst, ks + 1, (ks + 1) & 1);
            const int cur = ks & 1;
#pragma unroll
            for (int mi = 0; mi < 4; mi++)
#pragma unroll
                for (int ni = 0; ni < 4; ni++)
                    MMA_TF32(acc[mi][ni], af[cur][mi], &bf[cur][ni >> 1][(ni & 1) * 2]);
        }
        cst += STAGE_BYTES; if (cst == NSTAGE * STAGE_BYTES) cst = 0;
    }

    // ======================= epilogues =======================
    if (EPI == EPI_PROJ) {
        bias += (long)bz * DIM;
#pragma unroll
        for (int mi = 0; mi < 4; mi++) {
            const int row0 = bm + wm + mi * 16 + g;
#pragma unroll
            for (int ni = 0; ni < 4; ni++) {
                const int col = bn + wn + ni * 8 + 2 * t;
                const float bx2 = bias[col], by2 = bias[col + 1];
                float2 v0, v1;
                v0.x = tf32round(acc[mi][ni][0] + bx2);
                v0.y = tf32round(acc[mi][ni][1] + by2);
                v1.x = tf32round(acc[mi][ni][2] + bx2);
                v1.y = tf32round(acc[mi][ni][3] + by2);
                *(float2*)(C + (long)row0 * LDC + col)       = v0;
                *(float2*)(C + (long)(row0 + 8) * LDC + col) = v1;
            }
        }
    } else if (EPI == EPI_PROJT) {
#pragma unroll
        for (int mi = 0; mi < 4; mi++) {
            const int row0 = bm + wm + mi * 16 + g;
            const float b0 = bias[row0];
            const float b8 = bias[row0 + 8];
#pragma unroll
            for (int ni = 0; ni < 4; ni++) {
                const int col = bn + wn + ni * 8 + 2 * t;
                float2 v0, v1;
                v0.x = tf32round(acc[mi][ni][0] + b0);
                v0.y = tf32round(acc[mi][ni][1] + b0);
                v1.x = tf32round(acc[mi][ni][2] + b8);
                v1.y = tf32round(acc[mi][ni][3] + b8);
                *(float2*)(C + (long)row0 * LDC + col)       = v0;
                *(float2*)(C + (long)(row0 + 8) * LDC + col) = v1;
            }
        }
    } else if (EPI == EPI_SOFT) {
        mask += (long)bz * SEQ;
        int mk[8];
#pragma unroll
        for (int ni = 0; ni < 4; ni++) {
            const int col = bn + wn + ni * 8 + 2 * t;
            mk[ni * 2]     = mask[col];
            mk[ni * 2 + 1] = mask[col + 1];
        }
        __syncthreads();                       // smem stages -> scratch reuse
        float* part = (float*)smraw;           // [4][128] floats
        const int wnidx = wid & 3;
#pragma unroll
        for (int mi = 0; mi < 4; mi++) {
            const int rloc = wm + mi * 16 + g; // 0..127
            const int row0 = bm + rloc;
            float s0 = 0.f, s8 = 0.f;
#pragma unroll
            for (int ni = 0; ni < 4; ni++) {
                const int col = bn + wn + ni * 8 + 2 * t;
                float e0 = mk[ni * 2]     ? tf32round(__expf(acc[mi][ni][0] * scale)) : 0.f;
                float e1 = mk[ni * 2 + 1] ? tf32round(__expf(acc[mi][ni][1] * scale)) : 0.f;
                float e2 = mk[ni * 2]     ? tf32round(__expf(acc[mi][ni][2] * scale)) : 0.f;
                float e3 = mk[ni * 2 + 1] ? tf32round(__expf(acc[mi][ni][3] * scale)) : 0.f;
                *(float2*)(C + (long)row0 * LDC + col)       = make_float2(e0, e1);
                *(float2*)(C + (long)(row0 + 8) * LDC + col) = make_float2(e2, e3);
                s0 += e0 + e1;
                s8 += e2 + e3;
            }
            s0 += __shfl_xor_sync(0xFFFFFFFF, s0, 1);
            s0 += __shfl_xor_sync(0xFFFFFFFF, s0, 2);
            s8 += __shfl_xor_sync(0xFFFFFFFF, s8, 1);
            s8 += __shfl_xor_sync(0xFFFFFFFF, s8, 2);
            if (t == 0) {
                part[wnidx * 128 + rloc]     = s0;
                part[wnidx * 128 + rloc + 8] = s8;
            }
        }
        __syncthreads();
        if (tid < 128) {
            const float r = part[tid] + part[128 + tid] + part[256 + tid] + part[384 + tid];
            spart[(long)bx * (BB * SEQ) + (long)bz * SEQ + bm + tid] = r;
        }
    } else { // EPI_AV
        rsum += (long)bz * SEQ;
#pragma unroll
        for (int mi = 0; mi < 4; mi++) {
            const int row0 = bm + wm + mi * 16 + g;
            const float inv0 = 1.f / rsum[row0];
            const float inv8 = 1.f / rsum[row0 + 8];
#pragma unroll
            for (int ni = 0; ni < 4; ni++) {
                const int col = bn + wn + ni * 8 + 2 * t;
                float2 v0, v1;
                v0.x = acc[mi][ni][0] * inv0;
                v0.y = acc[mi][ni][1] * inv0;
                v1.x = acc[mi][ni][2] * inv8;
                v1.y = acc[mi][ni][3] * inv8;
                *(float2*)(C + (long)row0 * LDC + col)       = v0;
                *(float2*)(C + (long)(row0 + 8) * LDC + col) = v1;
            }
        }
    }
}

// ---------------------------------------------------------------------------
// Thin wrappers
// ---------------------------------------------------------------------------
template<int LDA, int LDB, int LDC, int K, int EPI>
__global__ void __launch_bounds__(256, 2)
gemm_mma(const float* __restrict__ A, const float* __restrict__ B,
         float* __restrict__ C,
         const float* __restrict__ bias, const int* __restrict__ mask,
         float* __restrict__ spart, const float* __restrict__ rsum,
         long sA, long sB, long sC, float scale)
{
    extern __shared__ char smraw[];
    gemm_body<LDA, LDB, LDC, K, EPI>(blockIdx.x, blockIdx.y, blockIdx.z,
                                     A, B, C, bias, mask, spart, rsum,
                                     sA, sB, sC, scale, smraw);
}

// Fused Q/K projection + transposed V projection in one launch.
// Flat grid of 1536 CTAs:
//   [0, 1024):  proj  (gx=4, gy=128, gz=2)  QK[z] = Xr @ W[z]^T + b[z]
//   [1024,1536): projT (gx=16, gy=4, gz=8)  Vt[b] = Wv @ Xr[b]^T + bv
__global__ void __launch_bounds__(256, 2)
proj_fused(const float* __restrict__ Xr, const float* __restrict__ Wr,
           float* __restrict__ QK, float* __restrict__ Vt,
           const float* __restrict__ bias)
{
    extern __shared__ char smraw[];
    const int idx = blockIdx.x;
    const long PLANE = (long)BB * SEQ * DIM;
    if (idx < 1024) {
        const int z   = idx >> 9;          // 0..1
        const int rem = idx & 511;
        gemm_body<DIM, DIM, DIM, DIM, EPI_PROJ>(
            rem & 3, rem >> 2, z,
            Xr, Wr, QK, bias, nullptr, nullptr, nullptr,
            0, (long)DIM * DIM, PLANE, 1.f, smraw);
    } else {
        const int i2  = idx - 1024;
        const int bz  = i2 >> 6;           // 0..7
        const int rem = i2 & 63;
        gemm_body<DIM, DIM, SEQ, DIM, EPI_PROJT>(
            rem & 15, rem >> 4, bz,
            Wr + 2L * DIM * DIM, Xr, Vt, bias + 2L * DIM,
            nullptr, nullptr, nullptr,
            0, (long)SEQ * DIM, (long)SEQ * DIM, 1.f, smraw);
    }
}

// ---------------------------------------------------------------------------
// Fold 16 per-coltile partial sums -> full row sums. Deterministic.
// ---------------------------------------------------------------------------
__global__ __launch_bounds__(256) void rowsum_kernel(
    const float* __restrict__ spart, float* __restrict__ rsum)
{
    const int r = blockIdx.x * blockDim.x + threadIdx.x;
    float s = 0.f;
#pragma unroll
    for (int t = 0; t < 16; t++)
        s += spart[(long)t * (BB * SEQ) + r];
    rsum[r] = s;
}

// ---------------------------------------------------------------------------
// Single prepass: round x -> Xr, Wq/Wk/Wv -> Wr slots, pack biases.
// ---------------------------------------------------------------------------
__global__ __launch_bounds__(256) void prep_kernel(
    const float4* __restrict__ x,
    const float4* __restrict__ wq, const float4* __restrict__ wk,
    const float4* __restrict__ wv,
    const float4* __restrict__ bq, const float4* __restrict__ bk,
    const float4* __restrict__ bv,
    float4* __restrict__ xr, float4* __restrict__ wr, float4* __restrict__ bdst,
    int xN4, int wN4)
{
    const int i = blockIdx.x * blockDim.x + threadIdx.x;
    auto rnd = [](float4 v) {
        v.x = tf32round(v.x); v.y = tf32round(v.y);
        v.z = tf32round(v.z); v.w = tf32round(v.w);
        return v;
    };
    if (i < xN4) {
        xr[i] = rnd(x[i]);
    } else {
        int j = i - xN4;
        if (j < 3 * wN4) {
            const int s = j / wN4, o = j - s * wN4;
            const float4* src = (s == 0) ? wq : (s == 1) ? wk : wv;
            wr[s * wN4 + o] = rnd(src[o]);
        } else {
            int k = j - 3 * wN4;
            if (k < 3 * (DIM / 4)) {
                const int s = k / (DIM / 4), o = k - s * (DIM / 4);
                const float4* src = (s == 0) ? bq : (s == 1) ? bk : bv;
                bdst[s * (DIM / 4) + o] = src[o];
            }
        }
    }
}

// ---------------------------------------------------------------------------
extern "C" void kernel_launch(void* const* d_in, const int* in_sizes, int n_in,
                              void* d_out, int out_size)
{
    const float* x    = (const float*)d_in[0];
    const int*   mask = (const int*)  d_in[1];
    const float* Wk   = (const float*)d_in[2];
    const float* bk   = (const float*)d_in[3];
    const float* Wq   = (const float*)d_in[4];
    const float* bq   = (const float*)d_in[5];
    const float* Wv   = (const float*)d_in[6];
    const float* bv   = (const float*)d_in[7];
    float* out = (float*)d_out;

    float *QK, *Vt, *S, *Xr, *Wr, *bias, *Spart, *rsum;
    cudaGetSymbolAddress((void**)&QK,    g_QK);
    cudaGetSymbolAddress((void**)&Vt,    g_Vt);
    cudaGetSymbolAddress((void**)&S,     g_S);
    cudaGetSymbolAddress((void**)&Xr,    g_Xr);
    cudaGetSymbolAddress((void**)&Wr,    g_Wr);
    cudaGetSymbolAddress((void**)&bias,  g_b);
    cudaGetSymbolAddress((void**)&Spart, g_Spart);
    cudaGetSymbolAddress((void**)&rsum,  g_rsum);

    const size_t PLANE = (size_t)BB * SEQ * DIM;
    float* Q  = QK;
    float* Kp = QK + PLANE;

    auto scorK = gemm_mma<DIM, DIM, SEQ, DIM, EPI_SOFT>;
    auto avK   = gemm_mma<SEQ, SEQ, DIM, SEQ, EPI_AV>;
    cudaFuncSetAttribute(proj_fused, cudaFuncAttributeMaxDynamicSharedMemorySize, GEMM_SMEM);
    cudaFuncSetAttribute(scorK, cudaFuncAttributeMaxDynamicSharedMemorySize, GEMM_SMEM);
    cudaFuncSetAttribute(avK,   cudaFuncAttributeMaxDynamicSharedMemorySize, GEMM_SMEM);

    // single prepass launch (Wr slots: 0=Wq, 1=Wk, 2=Wv; bias: bq|bk|bv)
    const int xN4 = BB * SEQ * DIM / 4;
    const int wN4 = DIM * DIM / 4;
    const int tot = xN4 + 3 * wN4 + 3 * (DIM / 4);
    prep_kernel<<<(tot + 255) / 256, 256>>>(
        (const float4*)x,
        (const float4*)Wq, (const float4*)Wk, (const float4*)Wv,
        (const float4*)bq, (const float4*)bk, (const float4*)bv,
        (float4*)Xr, (float4*)Wr, (float4*)bias, xN4, wN4);

    // fused Q/K projection + transposed V projection (one 1536-CTA launch)
    proj_fused<<<1536, 256, GEMM_SMEM>>>(Xr, Wr, QK, Vt, bias);

    // scores + masked exp + partial row sums:  P[b] = exp(Q K^T / sqrt(D))
    const float inv_sqrt_d = 0.044194173824159216f;
    dim3 gs(SEQ / TN, SEQ / TM, BB);
    scorK<<<gs, 256, GEMM_SMEM>>>(Q, Kp, S, nullptr, mask, Spart, nullptr,
                                  (long)SEQ * DIM, (long)SEQ * DIM, (long)SEQ * SEQ,
                                  inv_sqrt_d);

    // fold partial sums (16 col-tiles of 128)
    rowsum_kernel<<<(BB * SEQ) / 256, 256>>>(Spart, rsum);

    // out[b] = (P[b] @ Vt[b]^T) / rowsum
    dim3 ga(DIM / TN, SEQ / TM, BB);
    avK<<<ga, 256, GEMM_SMEM>>>(S, Vt, out, nullptr, nullptr, nullptr, rsum,
                                (long)SEQ * SEQ, (long)SEQ * DIM, (long)SEQ * DIM,
                                1.f);
}